// round 2
// baseline (speedup 1.0000x reference)
#include <cuda_runtime.h>
#include <cstdint>
#include <cstddef>

// ----------------------------------------------------------------------------
// GraphSAGE 2-layer forward (mean aggregation), fp32 end-to-end.
//   h   = relu( mean_agg(x, src1->dst1) @ W1_l^T + b1_l + x[:N1] @ W1_r^T )
//   out = relu( mean_agg(h, src2->dst2) @ W2_l^T + b2_l + h[:N2] @ W2_r^T )
// ----------------------------------------------------------------------------

static constexpr int D  = 128;
static constexpr int N1 = 50000;
static constexpr int N2 = 5000;

// Scratch (static __device__ — no allocations allowed)
__device__ float g_agg1[(size_t)N1 * D];
__device__ float g_cnt1[N1];
__device__ float g_h[(size_t)N1 * D];
__device__ float g_agg2[(size_t)N2 * D];
__device__ float g_cnt2[N2];

// ---------------------------------------------------------------- helpers ---
__device__ __forceinline__ unsigned long long f32x2_pack(float lo, float hi) {
    unsigned long long r;
    asm("mov.b64 %0, {%1, %2};" : "=l"(r) : "f"(lo), "f"(hi));
    return r;
}
__device__ __forceinline__ void f32x2_unpack(unsigned long long v, float& lo, float& hi) {
    asm("mov.b64 {%0, %1}, %2;" : "=f"(lo), "=f"(hi) : "l"(v));
}
__device__ __forceinline__ unsigned long long f32x2_fma(unsigned long long a,
                                                        unsigned long long b,
                                                        unsigned long long c) {
    unsigned long long d;
    asm("fma.rn.f32x2 %0, %1, %2, %3;" : "=l"(d) : "l"(a), "l"(b), "l"(c));
    return d;
}

// ------------------------------------------------------------------- zero ---
__global__ void zero_kernel() {
    int i = blockIdx.x * blockDim.x + threadIdx.x;
    int stride = gridDim.x * blockDim.x;
    for (int idx = i; idx < N1 * D; idx += stride) g_agg1[idx] = 0.0f;
    for (int idx = i; idx < N2 * D; idx += stride) g_agg2[idx] = 0.0f;
    for (int idx = i; idx < N1; idx += stride) g_cnt1[idx] = 0.0f;
    for (int idx = i; idx < N2; idx += stride) g_cnt2[idx] = 0.0f;
}

// ---------------------------------------------------------------- scatter ---
// One warp per edge: gather a 128-float row of xs, vector-reduce into agg[dst].
__global__ void scatter_kernel(const float* __restrict__ xs,
                               const int* __restrict__ src,
                               const int* __restrict__ dst,
                               int E,
                               float* __restrict__ agg,
                               float* __restrict__ cnt) {
    int warp = (blockIdx.x * blockDim.x + threadIdx.x) >> 5;
    int lane = threadIdx.x & 31;
    if (warp >= E) return;
    int s = __ldg(src + warp);
    int d = __ldg(dst + warp);
    float4 v = *reinterpret_cast<const float4*>(xs + (size_t)s * D + lane * 4);
    float* p = agg + (size_t)d * D + lane * 4;
    asm volatile("red.global.add.v4.f32 [%0], {%1, %2, %3, %4};"
                 :: "l"(p), "f"(v.x), "f"(v.y), "f"(v.z), "f"(v.w) : "memory");
    if (lane == 0) atomicAdd(cnt + d, 1.0f);
}

// ------------------------------------------------------------------- gemm ---
// out[m][n] = relu( sum_k mean[m][k]*Wl[n][k] + bias[n] + sum_k xdst[m][k]*Wr[n][k] )
// mean[m][k] = agg[m][k] / max(cnt[m], 1)
// Block covers BM rows x all BN(=N) cols. Concatenated K = 256 (mean | xdst).
// Weights live transposed in smem for the whole block; A streamed in 32-wide
// K-chunks with register prefetch; inner product uses packed fma.rn.f32x2.
template <int BM, int BN, int MR, int NR>
__global__ __launch_bounds__(256) void sage_gemm(
    const float* __restrict__ agg, const float* __restrict__ cnt,
    const float* __restrict__ xdst, const float* __restrict__ Wl,
    const float* __restrict__ Wr, const float* __restrict__ bias,
    float* __restrict__ out, int M) {
    constexpr int KC = 256;
    constexpr int KB = 32;
    constexpr int NCH = KC / KB;          // 8 chunks
    constexpr int BNP = BN + 4;           // padded smem stride
    constexpr int TX = BN / NR;           // threads along n
    constexpr int TY = BM / MR;           // threads along m
    constexpr int THREADS = TX * TY;      // 256
    constexpr int LD4 = (BM * KB / 4) / THREADS;

    extern __shared__ float smem[];
    float* Wc = smem;                 // [KC][BNP]  Wc[k][n]
    float* As = smem + KC * BNP;      // [KB][BM]   As[kk][r]

    const int t = threadIdx.x;
    const int tn = t % TX;
    const int tm = t / TX;
    const int row0 = blockIdx.x * BM;

    // ---- weights, transposed: Wc[k][n] = Wl[n][k]; Wc[128+k][n] = Wr[n][k]
    for (int f = t; f < BN * 32; f += THREADS) {
        int n = f >> 5;
        int kq = f & 31;
        float4 vl = *reinterpret_cast<const float4*>(Wl + n * 128 + kq * 4);
        float4 vr = *reinterpret_cast<const float4*>(Wr + n * 128 + kq * 4);
        const float* pl = &vl.x;
        const float* pr = &vr.x;
#pragma unroll
        for (int i = 0; i < 4; i++) {
            Wc[(kq * 4 + i) * BNP + n] = pl[i];
            Wc[(128 + kq * 4 + i) * BNP + n] = pr[i];
        }
    }

    int rj[LD4], qj[LD4];
#pragma unroll
    for (int j = 0; j < LD4; j++) {
        int fid = t + j * THREADS;
        rj[j] = fid % BM;
        qj[j] = fid / BM;  // 0..7 (float4 index within 32-wide K chunk)
    }

    float4 areg[LD4];

    auto load_chunk = [&](int c) {
        int kc = c * KB;
#pragma unroll
        for (int j = 0; j < LD4; j++) {
            int row = row0 + rj[j];
            if (row >= M) row = M - 1;      // dummy row; store suppressed later
            float4 v;
            if (kc < 128) {
                v = *reinterpret_cast<const float4*>(agg + (size_t)row * 128 + kc + qj[j] * 4);
                float s = 1.0f / fmaxf(__ldg(cnt + row), 1.0f);
                v.x *= s; v.y *= s; v.z *= s; v.w *= s;
            } else {
                v = *reinterpret_cast<const float4*>(xdst + (size_t)row * 128 + (kc - 128) + qj[j] * 4);
            }
            areg[j] = v;
        }
    };
    auto store_chunk = [&]() {
#pragma unroll
        for (int j = 0; j < LD4; j++) {
            const float* pv = &areg[j].x;
#pragma unroll
            for (int i = 0; i < 4; i++)
                As[(qj[j] * 4 + i) * BM + rj[j]] = pv[i];
        }
    };

    unsigned long long acc[MR][NR / 2];
#pragma unroll
    for (int i = 0; i < MR; i++)
#pragma unroll
        for (int j = 0; j < NR / 2; j++) acc[i][j] = 0ull;

    load_chunk(0);
    store_chunk();
    __syncthreads();

    for (int c = 0; c < NCH; c++) {
        if (c + 1 < NCH) load_chunk(c + 1);  // register prefetch of next chunk
        const int kb = c * KB;
#pragma unroll 8
        for (int kk = 0; kk < KB; kk++) {
            float a[MR];
#pragma unroll
            for (int v4 = 0; v4 < MR / 4; v4++) {
                float4 av = *reinterpret_cast<const float4*>(&As[kk * BM + tm * MR + v4 * 4]);
                a[v4 * 4 + 0] = av.x; a[v4 * 4 + 1] = av.y;
                a[v4 * 4 + 2] = av.z; a[v4 * 4 + 3] = av.w;
            }
            unsigned long long wp[NR / 2];
#pragma unroll
            for (int v4 = 0; v4 < NR / 4; v4++) {
                float4 wv = *reinterpret_cast<const float4*>(&Wc[(kb + kk) * BNP + tn * NR + v4 * 4]);
                wp[v4 * 2 + 0] = f32x2_pack(wv.x, wv.y);
                wp[v4 * 2 + 1] = f32x2_pack(wv.z, wv.w);
            }
#pragma unroll
            for (int i = 0; i < MR; i++) {
                unsigned long long ap = f32x2_pack(a[i], a[i]);
#pragma unroll
                for (int jp = 0; jp < NR / 2; jp++)
                    acc[i][jp] = f32x2_fma(ap, wp[jp], acc[i][jp]);
            }
        }
        __syncthreads();
        if (c + 1 < NCH) {
            store_chunk();
            __syncthreads();
        }
    }

    // ---- epilogue: + bias, relu, store
    float bs[NR];
#pragma unroll
    for (int j = 0; j < NR; j++) bs[j] = __ldg(bias + tn * NR + j);

#pragma unroll
    for (int i = 0; i < MR; i++) {
        int row = row0 + tm * MR + i;
        if (row >= M) continue;
        float o[NR];
#pragma unroll
        for (int jp = 0; jp < NR / 2; jp++)
            f32x2_unpack(acc[i][jp], o[2 * jp], o[2 * jp + 1]);
#pragma unroll
        for (int j = 0; j < NR; j++) o[j] = fmaxf(o[j] + bs[j], 0.0f);
#pragma unroll
        for (int v4 = 0; v4 < NR / 4; v4++) {
            float4 ov = make_float4(o[v4 * 4 + 0], o[v4 * 4 + 1], o[v4 * 4 + 2], o[v4 * 4 + 3]);
            *reinterpret_cast<float4*>(out + (size_t)row * BN + tn * NR + v4 * 4) = ov;
        }
    }
}

// ----------------------------------------------------------------- launch ---
extern "C" void kernel_launch(void* const* d_in, const int* in_sizes, int n_in,
                              void* d_out, int out_size) {
    const float* x   = (const float*)d_in[0];
    const float* W1l = (const float*)d_in[1];
    const float* b1l = (const float*)d_in[2];
    const float* W1r = (const float*)d_in[3];
    const float* W2l = (const float*)d_in[4];
    const float* b2l = (const float*)d_in[5];
    const float* W2r = (const float*)d_in[6];
    const int* src1  = (const int*)d_in[7];
    const int* dst1  = (const int*)d_in[8];
    const int* src2  = (const int*)d_in[9];
    const int* dst2  = (const int*)d_in[10];
    const int E1 = in_sizes[7];
    const int E2 = in_sizes[9];

    constexpr int BM1 = 128, BN1 = 128;
    constexpr int BM2 = 64,  BN2 = 64;
    const size_t sm1 = (size_t)(256 * (BN1 + 4) + 32 * BM1) * sizeof(float);
    const size_t sm2 = (size_t)(256 * (BN2 + 4) + 32 * BM2) * sizeof(float);

    // One-time host-side setup (capture-safe either way, but do it once).
    struct Setup {
        float *agg1, *cnt1, *h, *agg2, *cnt2;
        Setup(size_t s1, size_t s2) {
            cudaGetSymbolAddress((void**)&agg1, g_agg1);
            cudaGetSymbolAddress((void**)&cnt1, g_cnt1);
            cudaGetSymbolAddress((void**)&h,    g_h);
            cudaGetSymbolAddress((void**)&agg2, g_agg2);
            cudaGetSymbolAddress((void**)&cnt2, g_cnt2);
            cudaFuncSetAttribute((const void*)sage_gemm<BM1, BN1, 8, 8>,
                                 cudaFuncAttributeMaxDynamicSharedMemorySize, (int)s1);
            cudaFuncSetAttribute((const void*)sage_gemm<BM2, BN2, 4, 4>,
                                 cudaFuncAttributeMaxDynamicSharedMemorySize, (int)s2);
        }
    };
    static Setup su(sm1, sm2);

    // 1) zero accumulators
    zero_kernel<<<25000, 256>>>();

    // 2) layer-1 scatter (warp per edge)
    {
        long long threads = (long long)E1 * 32;
        int blocks = (int)((threads + 255) / 256);
        scatter_kernel<<<blocks, 256>>>(x, src1, dst1, E1, su.agg1, su.cnt1);
    }

    // 3) layer-1 fused GEMM -> h [N1,128]
    sage_gemm<BM1, BN1, 8, 8><<<(N1 + BM1 - 1) / BM1, 256, sm1>>>(
        su.agg1, su.cnt1, x, W1l, W1r, b1l, su.h, N1);

    // 4) layer-2 scatter
    {
        long long threads = (long long)E2 * 32;
        int blocks = (int)((threads + 255) / 256);
        scatter_kernel<<<blocks, 256>>>(su.h, src2, dst2, E2, su.agg2, su.cnt2);
    }

    // 5) layer-2 fused GEMM -> d_out [N2,64]
    sage_gemm<BM2, BN2, 4, 4><<<(N2 + BM2 - 1) / BM2, 256, sm2>>>(
        su.agg2, su.cnt2, su.h, W2l, W2r, b2l, (float*)d_out, N2);
}

// round 4
// speedup vs baseline: 1.1869x; 1.1869x over previous
#include <cuda_runtime.h>
#include <cstdint>
#include <cstddef>

// ----------------------------------------------------------------------------
// GraphSAGE 2-layer forward (mean aggregation), fp32 end-to-end.
//   h   = relu( mean_agg(x, src1->dst1) @ W1_l^T + b1_l + x[:N1] @ W1_r^T )
//   out = relu( mean_agg(h, src2->dst2) @ W2_l^T + b2_l + h[:N2] @ W2_r^T )
// ----------------------------------------------------------------------------

static constexpr int D  = 128;
static constexpr int N1 = 50000;
static constexpr int N2 = 5000;

// Scratch (static __device__ — no allocations allowed)
__device__ float g_agg1[(size_t)N1 * D];
__device__ float g_cnt1[N1];
__device__ float g_h[(size_t)N1 * D];
__device__ float g_agg2[(size_t)N2 * D];
__device__ float g_cnt2[N2];

// ---------------------------------------------------------------- helpers ---
__device__ __forceinline__ unsigned long long f32x2_pack(float lo, float hi) {
    unsigned long long r;
    asm("mov.b64 %0, {%1, %2};" : "=l"(r) : "f"(lo), "f"(hi));
    return r;
}
__device__ __forceinline__ void f32x2_unpack(unsigned long long v, float& lo, float& hi) {
    asm("mov.b64 {%0, %1}, %2;" : "=f"(lo), "=f"(hi) : "l"(v));
}
__device__ __forceinline__ unsigned long long f32x2_fma(unsigned long long a,
                                                        unsigned long long b,
                                                        unsigned long long c) {
    unsigned long long d;
    asm("fma.rn.f32x2 %0, %1, %2, %3;" : "=l"(d) : "l"(a), "l"(b), "l"(c));
    return d;
}

// ------------------------------------------------------------------- zero ---
__global__ void zero_kernel() {
    int i = blockIdx.x * blockDim.x + threadIdx.x;
    int stride = gridDim.x * blockDim.x;
    float4 z = make_float4(0.f, 0.f, 0.f, 0.f);
    for (int idx = i; idx < N1 * D / 4; idx += stride)
        reinterpret_cast<float4*>(g_agg1)[idx] = z;
    for (int idx = i; idx < N2 * D / 4; idx += stride)
        reinterpret_cast<float4*>(g_agg2)[idx] = z;
    for (int idx = i; idx < N1; idx += stride) g_cnt1[idx] = 0.0f;
    for (int idx = i; idx < N2; idx += stride) g_cnt2[idx] = 0.0f;
}

// ---------------------------------------------------------------- scatter ---
// EPW edges per warp. Front-batch the EPW row-gathers (per-thread MLP = EPW),
// then issue the fire-and-forget vector reductions. Only exposed latency is
// one load batch per EPW edges instead of per edge.
template <int EPW>
__global__ __launch_bounds__(256) void scatter_kernel(
    const float* __restrict__ xs,
    const int* __restrict__ src,
    const int* __restrict__ dst,
    int E,
    float* __restrict__ agg,
    float* __restrict__ cnt) {
    const int gw = (blockIdx.x * blockDim.x + threadIdx.x) >> 5;
    const int lane = threadIdx.x & 31;
    const long long base = (long long)gw * EPW;
    if (base >= E) return;
    const int n = (int)min((long long)EPW, (long long)E - base);

    // lanes 0..EPW-1 fetch indices; broadcast via shfl
    int si = 0, di = 0;
    if (lane < n) {
        si = __ldg(src + base + lane);
        di = __ldg(dst + base + lane);
    }

    float4 v[EPW];
#pragma unroll
    for (int j = 0; j < EPW; j++) {
        int s = __shfl_sync(0xffffffffu, si, j);
        if (j < n)
            v[j] = *reinterpret_cast<const float4*>(xs + (size_t)s * D + lane * 4);
    }

#pragma unroll
    for (int j = 0; j < EPW; j++) {
        int d = __shfl_sync(0xffffffffu, di, j);
        if (j < n) {
            float* p = agg + (size_t)d * D + lane * 4;
            asm volatile("red.global.add.v4.f32 [%0], {%1, %2, %3, %4};"
                         :: "l"(p), "f"(v[j].x), "f"(v[j].y), "f"(v[j].z), "f"(v[j].w)
                         : "memory");
            if (lane == j) atomicAdd(cnt + d, 1.0f);  // spread cnt atomics across lanes
        }
    }
}

// ------------------------------------------------------------------- gemm ---
// out[m][n] = relu( sum_k mean[m][k]*Wl[n][k] + bias[n] + sum_k xdst[m][k]*Wr[n][k] )
// mean[m][k] = agg[m][k] / max(cnt[m], 1).  Concatenated K = 256 (mean | xdst).
// Weights transposed in smem for the whole block; A streamed in 32-wide K
// chunks with register prefetch; inner product uses packed fma.rn.f32x2.
template <int BM, int BN, int MR, int NR>
__global__ __launch_bounds__(256) void sage_gemm(
    const float* __restrict__ agg, const float* __restrict__ cnt,
    const float* __restrict__ xdst, const float* __restrict__ Wl,
    const float* __restrict__ Wr, const float* __restrict__ bias,
    float* __restrict__ out, int M) {
    constexpr int KC = 256;
    constexpr int KB = 32;
    constexpr int NCH = KC / KB;
    constexpr int BNP = BN + 4;
    constexpr int TX = BN / NR;
    constexpr int TY = BM / MR;
    constexpr int THREADS = TX * TY;      // 256
    constexpr int LD4 = (BM * KB / 4) / THREADS;

    extern __shared__ float smem[];
    float* Wc = smem;                 // [KC][BNP]  Wc[k][n]
    float* As = smem + KC * BNP;      // [KB][BM]   As[kk][r]

    const int t = threadIdx.x;
    const int tn = t % TX;
    const int tm = t / TX;
    const int row0 = blockIdx.x * BM;

    for (int f = t; f < BN * 32; f += THREADS) {
        int n = f >> 5;
        int kq = f & 31;
        float4 vl = *reinterpret_cast<const float4*>(Wl + n * 128 + kq * 4);
        float4 vr = *reinterpret_cast<const float4*>(Wr + n * 128 + kq * 4);
        const float* pl = &vl.x;
        const float* pr = &vr.x;
#pragma unroll
        for (int i = 0; i < 4; i++) {
            Wc[(kq * 4 + i) * BNP + n] = pl[i];
            Wc[(128 + kq * 4 + i) * BNP + n] = pr[i];
        }
    }

    int rj[LD4], qj[LD4];
#pragma unroll
    for (int j = 0; j < LD4; j++) {
        int fid = t + j * THREADS;
        rj[j] = fid % BM;
        qj[j] = fid / BM;
    }

    float4 areg[LD4];

    auto load_chunk = [&](int c) {
        int kc = c * KB;
#pragma unroll
        for (int j = 0; j < LD4; j++) {
            int row = row0 + rj[j];
            if (row >= M) row = M - 1;
            float4 v;
            if (kc < 128) {
                v = *reinterpret_cast<const float4*>(agg + (size_t)row * 128 + kc + qj[j] * 4);
                float s = 1.0f / fmaxf(__ldg(cnt + row), 1.0f);
                v.x *= s; v.y *= s; v.z *= s; v.w *= s;
            } else {
                v = *reinterpret_cast<const float4*>(xdst + (size_t)row * 128 + (kc - 128) + qj[j] * 4);
            }
            areg[j] = v;
        }
    };
    auto store_chunk = [&]() {
#pragma unroll
        for (int j = 0; j < LD4; j++) {
            const float* pv = &areg[j].x;
#pragma unroll
            for (int i = 0; i < 4; i++)
                As[(qj[j] * 4 + i) * BM + rj[j]] = pv[i];
        }
    };

    unsigned long long acc[MR][NR / 2];
#pragma unroll
    for (int i = 0; i < MR; i++)
#pragma unroll
        for (int j = 0; j < NR / 2; j++) acc[i][j] = 0ull;

    load_chunk(0);
    store_chunk();
    __syncthreads();

    for (int c = 0; c < NCH; c++) {
        if (c + 1 < NCH) load_chunk(c + 1);
        const int kb = c * KB;
#pragma unroll 8
        for (int kk = 0; kk < KB; kk++) {
            float a[MR];
#pragma unroll
            for (int v4 = 0; v4 < MR / 4; v4++) {
                float4 av = *reinterpret_cast<const float4*>(&As[kk * BM + tm * MR + v4 * 4]);
                a[v4 * 4 + 0] = av.x; a[v4 * 4 + 1] = av.y;
                a[v4 * 4 + 2] = av.z; a[v4 * 4 + 3] = av.w;
            }
            unsigned long long wp[NR / 2];
#pragma unroll
            for (int v4 = 0; v4 < NR / 4; v4++) {
                float4 wv = *reinterpret_cast<const float4*>(&Wc[(kb + kk) * BNP + tn * NR + v4 * 4]);
                wp[v4 * 2 + 0] = f32x2_pack(wv.x, wv.y);
                wp[v4 * 2 + 1] = f32x2_pack(wv.z, wv.w);
            }
#pragma unroll
            for (int i = 0; i < MR; i++) {
                unsigned long long ap = f32x2_pack(a[i], a[i]);
#pragma unroll
                for (int jp = 0; jp < NR / 2; jp++)
                    acc[i][jp] = f32x2_fma(ap, wp[jp], acc[i][jp]);
            }
        }
        __syncthreads();
        if (c + 1 < NCH) {
            store_chunk();
            __syncthreads();
        }
    }

    float bs[NR];
#pragma unroll
    for (int j = 0; j < NR; j++) bs[j] = __ldg(bias + tn * NR + j);

#pragma unroll
    for (int i = 0; i < MR; i++) {
        int row = row0 + tm * MR + i;
        if (row >= M) continue;
        float o[NR];
#pragma unroll
        for (int jp = 0; jp < NR / 2; jp++)
            f32x2_unpack(acc[i][jp], o[2 * jp], o[2 * jp + 1]);
#pragma unroll
        for (int j = 0; j < NR; j++) o[j] = fmaxf(o[j] + bs[j], 0.0f);
#pragma unroll
        for (int v4 = 0; v4 < NR / 4; v4++) {
            float4 ov = make_float4(o[v4 * 4 + 0], o[v4 * 4 + 1], o[v4 * 4 + 2], o[v4 * 4 + 3]);
            *reinterpret_cast<float4*>(out + (size_t)row * BN + tn * NR + v4 * 4) = ov;
        }
    }
}

// ----------------------------------------------------------------- launch ---
extern "C" void kernel_launch(void* const* d_in, const int* in_sizes, int n_in,
                              void* d_out, int out_size) {
    const float* x   = (const float*)d_in[0];
    const float* W1l = (const float*)d_in[1];
    const float* b1l = (const float*)d_in[2];
    const float* W1r = (const float*)d_in[3];
    const float* W2l = (const float*)d_in[4];
    const float* b2l = (const float*)d_in[5];
    const float* W2r = (const float*)d_in[6];
    const int* src1  = (const int*)d_in[7];
    const int* dst1  = (const int*)d_in[8];
    const int* src2  = (const int*)d_in[9];
    const int* dst2  = (const int*)d_in[10];
    const int E1 = in_sizes[7];
    const int E2 = in_sizes[9];

    constexpr int BM1 = 128, BN1 = 128;
    constexpr int BM2 = 64,  BN2 = 64;
    const size_t sm1 = (size_t)(256 * (BN1 + 4) + 32 * BM1) * sizeof(float);
    const size_t sm2 = (size_t)(256 * (BN2 + 4) + 32 * BM2) * sizeof(float);

    struct Setup {
        float *agg1, *cnt1, *h, *agg2, *cnt2;
        Setup(size_t s1, size_t s2) {
            cudaGetSymbolAddress((void**)&agg1, g_agg1);
            cudaGetSymbolAddress((void**)&cnt1, g_cnt1);
            cudaGetSymbolAddress((void**)&h,    g_h);
            cudaGetSymbolAddress((void**)&agg2, g_agg2);
            cudaGetSymbolAddress((void**)&cnt2, g_cnt2);
            cudaFuncSetAttribute((const void*)sage_gemm<BM1, BN1, 8, 8>,
                                 cudaFuncAttributeMaxDynamicSharedMemorySize, (int)s1);
            cudaFuncSetAttribute((const void*)sage_gemm<BM2, BN2, 4, 4>,
                                 cudaFuncAttributeMaxDynamicSharedMemorySize, (int)s2);
        }
    };
    static Setup su(sm1, sm2);

    constexpr int EPW = 8;

    // 1) zero accumulators
    zero_kernel<<<2048, 256>>>();

    // 2) layer-1 scatter (8 edges per warp, MLP-batched)
    {
        long long warps = ((long long)E1 + EPW - 1) / EPW;
        int blocks = (int)((warps * 32 + 255) / 256);
        scatter_kernel<EPW><<<blocks, 256>>>(x, src1, dst1, E1, su.agg1, su.cnt1);
    }

    // 3) layer-1 fused GEMM -> h [N1,128]
    sage_gemm<BM1, BN1, 8, 8><<<(N1 + BM1 - 1) / BM1, 256, sm1>>>(
        su.agg1, su.cnt1, x, W1l, W1r, b1l, su.h, N1);

    // 4) layer-2 scatter
    {
        long long warps = ((long long)E2 + EPW - 1) / EPW;
        int blocks = (int)((warps * 32 + 255) / 256);
        scatter_kernel<EPW><<<blocks, 256>>>(su.h, src2, dst2, E2, su.agg2, su.cnt2);
    }

    // 5) layer-2 fused GEMM -> d_out [N2,64]
    sage_gemm<BM2, BN2, 4, 4><<<(N2 + BM2 - 1) / BM2, 256, sm2>>>(
        su.agg2, su.cnt2, su.h, W2l, W2r, b2l, (float*)d_out, N2);
}